// round 14
// baseline (speedup 1.0000x reference)
#include <cuda_runtime.h>
#include <cuda_bf16.h>
#include <cstdint>
#include <cstddef>

// Problem constants: B=16, T=2048, D=1024, E=4D=4096
#define BB 16
#define TT 2048
#define DD 1024
#define EE 4096

#define REC_BLOCKS 128
#define DPB (DD / REC_BLOCKS)

// ---------------------------------------------------------------------------
// Device scratch
// ---------------------------------------------------------------------------
__device__ float g_xg[(size_t)BB * TT * EE];

__device__ __nv_bfloat16 g_xhi[(size_t)BB * TT * DD];
__device__ __nv_bfloat16 g_xlo[(size_t)BB * TT * DD];
__device__ __nv_bfloat16 g_wihi[(size_t)DD * EE];
__device__ __nv_bfloat16 g_wilo[(size_t)DD * EE];

// h in mma A-fragment order, hi/lo interleaved per register.
__device__ __align__(16) uint32_t g_hfrag[2][64 * 32 * 8];

// Per-kslice flags: flag[ks] (256B apart) counts publications by the TWO
// producer blocks 2ks, 2ks+1.  h_t ready for kslice ks <=> flag >= 2(t+1).
__device__ unsigned g_flags[64 * 64];
__device__ unsigned g_endcnt;

// ---------------------------------------------------------------------------
// Helpers
// ---------------------------------------------------------------------------
__device__ __forceinline__ void mma4(float* c, const uint32_t* a,
                                     uint32_t b0, uint32_t b1) {
    asm volatile(
        "mma.sync.aligned.m16n8k16.row.col.f32.bf16.bf16.f32 "
        "{%0,%1,%2,%3}, {%4,%5,%6,%7}, {%8,%9}, {%0,%1,%2,%3};\n"
        : "+f"(c[0]), "+f"(c[1]), "+f"(c[2]), "+f"(c[3])
        : "r"(a[0]), "r"(a[1]), "r"(a[2]), "r"(a[3]), "r"(b0), "r"(b1));
}

__device__ __forceinline__ void mma_bf16(float4& c, const uint4& a,
                                         uint32_t b0, uint32_t b1) {
    asm volatile(
        "mma.sync.aligned.m16n8k16.row.col.f32.bf16.bf16.f32 "
        "{%0,%1,%2,%3}, {%4,%5,%6,%7}, {%8,%9}, {%0,%1,%2,%3};\n"
        : "+f"(c.x), "+f"(c.y), "+f"(c.z), "+f"(c.w)
        : "r"(a.x), "r"(a.y), "r"(a.z), "r"(a.w), "r"(b0), "r"(b1));
}

__device__ __forceinline__ void ldsm_x4(uint32_t* r, uint32_t addr) {
    asm volatile("ldmatrix.sync.aligned.m8n8.x4.shared.b16 {%0,%1,%2,%3}, [%4];"
        : "=r"(r[0]), "=r"(r[1]), "=r"(r[2]), "=r"(r[3]) : "r"(addr));
}
__device__ __forceinline__ void ldsm_x4_t(uint32_t* r, uint32_t addr) {
    asm volatile("ldmatrix.sync.aligned.m8n8.x4.trans.shared.b16 {%0,%1,%2,%3}, [%4];"
        : "=r"(r[0]), "=r"(r[1]), "=r"(r[2]), "=r"(r[3]) : "r"(addr));
}

__device__ __forceinline__ void split_bf16(float v, __nv_bfloat16& hi,
                                           __nv_bfloat16& lo) {
    hi = __float2bfloat16(v);
    lo = __float2bfloat16(v - __bfloat162float(hi));
}

__device__ __forceinline__ uint32_t pack_bf2(__nv_bfloat16 a, __nv_bfloat16 b) {
    return (uint32_t)__bfloat16_as_ushort(a) |
           ((uint32_t)__bfloat16_as_ushort(b) << 16);
}

__device__ __forceinline__ float fast_sigmoid(float x) {
    return __fdividef(1.f, 1.f + __expf(-x));
}
__device__ __forceinline__ float fast_tanh(float x) {
    return __fdividef(2.f, 1.f + __expf(-2.f * x)) - 1.f;
}

#define CP_ASYNC16(dst, src) \
    asm volatile("cp.async.cg.shared.global [%0], [%1], 16;" \
                 :: "r"(dst), "l"(src))
#define CP_COMMIT() asm volatile("cp.async.commit_group;" ::: "memory")
#define CP_WAIT2()  asm volatile("cp.async.wait_group 2;" ::: "memory")

// ---------------------------------------------------------------------------
// Phase 0: split fp32 -> bf16 hi/lo planes
// ---------------------------------------------------------------------------
__global__ __launch_bounds__(256) void split_kernel(
    const float* __restrict__ src,
    __nv_bfloat16* __restrict__ hi,
    __nv_bfloat16* __restrict__ lo,
    size_t n4)
{
    size_t i = (size_t)blockIdx.x * 256 + threadIdx.x;
    if (i >= n4) return;
    float4 v = ((const float4*)src)[i];
    __nv_bfloat16 h[4], l[4];
    split_bf16(v.x, h[0], l[0]);
    split_bf16(v.y, h[1], l[1]);
    split_bf16(v.z, h[2], l[2]);
    split_bf16(v.w, h[3], l[3]);
    ((uint2*)hi)[i] = make_uint2(pack_bf2(h[0], h[1]), pack_bf2(h[2], h[3]));
    ((uint2*)lo)[i] = make_uint2(pack_bf2(l[0], l[1]), pack_bf2(l[2], l[3]));
}

// ---------------------------------------------------------------------------
// Phase 1: xg = x @ Wi (3-pass bf16 MMA, cp.async 3-stage) — exact R5
// ---------------------------------------------------------------------------
#define A_STRIDE 40
#define B_STRIDE 136
#define A_PLANE (128 * A_STRIDE)
#define B_PLANE (32 * B_STRIDE)
#define STAGE_ELEMS (2 * A_PLANE + 2 * B_PLANE)
#define STAGE_BYTES (STAGE_ELEMS * 2)
#define GEMM_SMEM_BYTES (3 * STAGE_BYTES)

__global__ __launch_bounds__(256) void gemm_xg_mma(void)
{
    extern __shared__ __align__(16) __nv_bfloat16 gsm[];

    const int tid  = threadIdx.x;
    const int lane = tid & 31;
    const int w    = tid >> 5;
    const int wn   = w >> 2;
    const int wm   = w & 3;
    const int m0   = blockIdx.y * 128;
    const int n0   = blockIdx.x * 128;

    const uint32_t smem_u32 = (uint32_t)__cvta_generic_to_shared(gsm);

    auto issue_stage = [&](int stage, int kt) {
        const int k0 = kt * 32;
        uint32_t sb = smem_u32 + stage * STAGE_BYTES;
#pragma unroll
        for (int r = 0; r < 2; ++r) {
            int chunk = tid + 256 * r;
            int row   = chunk >> 2;
            int c8    = (chunk & 3) * 8;
            const __nv_bfloat16* sh = g_xhi + (size_t)(m0 + row) * DD + k0 + c8;
            const __nv_bfloat16* sl = g_xlo + (size_t)(m0 + row) * DD + k0 + c8;
            uint32_t dh = sb + (uint32_t)(row * A_STRIDE + c8) * 2;
            uint32_t dl = dh + A_PLANE * 2;
            CP_ASYNC16(dh, sh);
            CP_ASYNC16(dl, sl);
        }
        uint32_t bb = sb + 4 * A_PLANE;
#pragma unroll
        for (int r = 0; r < 2; ++r) {
            int chunk = tid + 256 * r;
            int row   = chunk >> 4;
            int c8    = (chunk & 15) * 8;
            const __nv_bfloat16* sh = g_wihi + (size_t)(k0 + row) * EE + n0 + c8;
            const __nv_bfloat16* sl = g_wilo + (size_t)(k0 + row) * EE + n0 + c8;
            uint32_t dh = bb + (uint32_t)(row * B_STRIDE + c8) * 2;
            uint32_t dl = dh + B_PLANE * 2;
            CP_ASYNC16(dh, sh);
            CP_ASYNC16(dl, sl);
        }
    };

    float acc[2][8][4];
#pragma unroll
    for (int mt = 0; mt < 2; ++mt)
#pragma unroll
        for (int nt = 0; nt < 8; ++nt)
#pragma unroll
            for (int i = 0; i < 4; ++i) acc[mt][nt][i] = 0.f;

    issue_stage(0, 0); CP_COMMIT();
    issue_stage(1, 1); CP_COMMIT();
    issue_stage(2, 2); CP_COMMIT();

    for (int it = 0; it < 32; ++it) {
        CP_WAIT2();
        __syncthreads();

        const int stage = it % 3;
        const uint32_t aBase = smem_u32 + stage * STAGE_BYTES;
        const uint32_t bBase = aBase + 4 * A_PLANE;

#pragma unroll
        for (int ks = 0; ks < 2; ++ks) {
            uint32_t afr[2][2][4];
#pragma unroll
            for (int mt = 0; mt < 2; ++mt)
#pragma unroll
                for (int p = 0; p < 2; ++p) {
                    uint32_t addr = aBase + p * (A_PLANE * 2)
                        + (uint32_t)((wm * 32 + mt * 16 + (lane & 15)) * (A_STRIDE * 2))
                        + (uint32_t)((ks * 16 + (lane >> 4) * 8) * 2);
                    ldsm_x4(afr[mt][p], addr);
                }
            uint32_t bfr[4][2][4];
#pragma unroll
            for (int np = 0; np < 4; ++np)
#pragma unroll
                for (int p = 0; p < 2; ++p) {
                    uint32_t addr = bBase + p * (B_PLANE * 2)
                        + (uint32_t)((ks * 16 + (lane & 15)) * (B_STRIDE * 2))
                        + (uint32_t)((wn * 64 + np * 16 + (lane >> 4) * 8) * 2);
                    ldsm_x4_t(bfr[np][p], addr);
                }
#pragma unroll
            for (int mt = 0; mt < 2; ++mt)
#pragma unroll
                for (int np = 0; np < 4; ++np)
#pragma unroll
                    for (int hf = 0; hf < 2; ++hf) {
                        int nt = np * 2 + hf;
                        float* c = acc[mt][nt];
                        uint32_t bh0 = bfr[np][0][hf * 2];
                        uint32_t bh1 = bfr[np][0][hf * 2 + 1];
                        uint32_t bl0 = bfr[np][1][hf * 2];
                        uint32_t bl1 = bfr[np][1][hf * 2 + 1];
                        mma4(c, afr[mt][0], bh0, bh1);
                        mma4(c, afr[mt][0], bl0, bl1);
                        mma4(c, afr[mt][1], bh0, bh1);
                    }
        }
        __syncthreads();
        if (it + 3 < 32) issue_stage(stage, it + 3);
        CP_COMMIT();
    }

#pragma unroll
    for (int mt = 0; mt < 2; ++mt)
#pragma unroll
        for (int nt = 0; nt < 8; ++nt) {
            int row = m0 + wm * 32 + mt * 16 + (lane >> 2);
            int col = n0 + wn * 64 + nt * 8 + (lane & 3) * 2;
            float* c = acc[mt][nt];
            __stcs((float2*)(g_xg + (size_t)row * EE + col),
                   make_float2(c[0], c[1]));
            __stcs((float2*)(g_xg + (size_t)(row + 8) * EE + col),
                   make_float2(c[2], c[3]));
        }
}

// ---------------------------------------------------------------------------
// Phase 2: persistent recurrence — R5 structure with PER-KSLICE flags.
// Warp w consumes kslices [8w,8w+8); kslice ks is produced by blocks
// 2ks, 2ks+1 only.  Wait for each kslice right before consuming it, so
// MMAs on ready kslices overlap waits on late ones.
// ---------------------------------------------------------------------------
#define W_WORDS (4 * 64 * 32 * 4)
#define RED_FLOATS (8 * 4 * 32 * 4)
#define REC_SMEM_BYTES (W_WORDS * 4 + 2 * RED_FLOATS * 4)

__global__ __launch_bounds__(256, 1) void lstm_rec_kernel(
    const float* __restrict__ carry,
    const float* __restrict__ Wh,
    const float* __restrict__ bias,
    float* __restrict__ dout)
{
    extern __shared__ uint32_t sm_w[];
    float* red = (float*)(sm_w + W_WORDS);

    const int tid  = threadIdx.x;
    const int w    = tid >> 5;
    const int lane = tid & 31;
    const int d0   = blockIdx.x * DPB;

    for (int idx = tid; idx < 4 * 64 * 32 * 2; idx += 256) {
        int n    = idx >> 12;
        int rem  = idx & 4095;
        int ks   = rem >> 6;
        int rem2 = rem & 63;
        int ln   = rem2 >> 1;
        int reg  = rem2 & 1;
        int tig  = ln & 3;
        int dl   = ln >> 2;
        int kb   = ks * 16 + reg * 8 + tig * 2;
        size_t col = (size_t)n * DD + d0 + dl;
        float v0 = Wh[(size_t)kb * EE + col];
        float v1 = Wh[(size_t)(kb + 1) * EE + col];
        __nv_bfloat16 h0, l0, h1, l1;
        split_bf16(v0, h0, l0);
        split_bf16(v1, h1, l1);
        uint32_t* wp = sm_w + (size_t)(((n * 64 + ks) * 32 + ln)) * 4;
        wp[reg]     = pack_bf2(h0, h1);
        wp[2 + reg] = pack_bf2(l0, l1);
    }

    float c_reg = 0.f, h_last = 0.f, bi = 0.f, bf_ = 0.f, bgt = 0.f, bo = 0.f;
    int pb = 0, pd = 0, pdg = 0, lane_c = 0, reg_c = 0;
    unsigned whoff = 0;
    int even = 0;
    const unsigned myflag = (unsigned)(blockIdx.x >> 1);   // kslice this block feeds

    if (tid < 128) {
        pd  = tid & 7;
        pb  = tid >> 3;
        pdg = d0 + pd;
        int ksp  = pdg >> 4;
        int cc   = pdg & 15;
        int lnp  = (pb & 7) * 4 + ((cc & 7) >> 1);
        int regp = ((pb >> 3) & 1) + 2 * ((cc >> 3) & 1);
        whoff = (unsigned)((ksp * 32 + lnp) * 8 + 2 * regp);
        even  = ((cc & 1) == 0);
        lane_c = (pb & 7) * 4 + (pd >> 1);
        reg_c  = 2 * (pb >> 3) + (pd & 1);

        c_reg = carry[((size_t)pb * DD + pdg) * 2 + 1];
        float h0v = carry[((size_t)pb * DD + pdg) * 2 + 0];
        bi  = bias[pdg];
        bf_ = bias[DD + pdg];
        bgt = bias[2 * DD + pdg];
        bo  = bias[3 * DD + pdg];

        __nv_bfloat16 hhi, hlo;
        split_bf16(h0v, hhi, hlo);
        uint32_t v  = pack_bf2(hhi, hlo);
        uint32_t pv = __shfl_xor_sync(0xffffffffu, v, 1);
        if (even) {
            uint2 pr;
            pr.x = (v & 0xffffu) | ((pv & 0xffffu) << 16);
            pr.y = (v >> 16) | ((pv >> 16) << 16);
            *(uint2*)(g_hfrag[0] + whoff) = pr;
        }
    }
    __syncthreads();
    if (tid == 0) {
        asm volatile("red.release.gpu.global.add.u32 [%0], %1;"
                     :: "l"(&g_flags[myflag * 64]), "r"(1u) : "memory");
    }

    float* nc = dout + (size_t)BB * TT * DD;

    for (int t = 0; t < TT; ++t) {
        float xgi = 0.f, xgf = 0.f, xgg = 0.f, xgo = 0.f;
        if (tid < 128) {
            const float* xr = g_xg + ((size_t)pb * TT + t) * EE + pdg;
            xgi = __ldg(xr);
            xgf = __ldg(xr + DD);
            xgg = __ldg(xr + 2 * DD);
            xgo = __ldg(xr + 3 * DD);
        }

        float4 acc[4];
#pragma unroll
        for (int n = 0; n < 4; ++n) acc[n] = make_float4(0.f, 0.f, 0.f, 0.f);

        const uint4* ab = (const uint4*)g_hfrag[t & 1];
        const unsigned tgt2 = 2u * (unsigned)(t + 1);
#pragma unroll
        for (int j = 0; j < 8; ++j) {
            int ks = w * 8 + j;
            // wait for kslice ks's TWO producers (blocks 2ks, 2ks+1)
            {
                unsigned v;
                do {
                    asm volatile("ld.global.acquire.gpu.u32 %0, [%1];"
                                 : "=r"(v) : "l"(&g_flags[(unsigned)ks * 64])
                                 : "memory");
                } while (v < tgt2);
            }
            uint4 q0 = __ldcg(ab + (ks * 32 + lane) * 2);
            uint4 q1 = __ldcg(ab + (ks * 32 + lane) * 2 + 1);
            uint4 ahi = make_uint4(q0.x, q0.z, q1.x, q1.z);
            uint4 alo = make_uint4(q0.y, q0.w, q1.y, q1.w);
#pragma unroll
            for (int n = 0; n < 4; ++n) {
                uint4 b = *(const uint4*)(sm_w + (size_t)(((n * 64 + ks) * 32 + lane)) * 4);
                mma_bf16(acc[n], ahi, b.x, b.y);
                mma_bf16(acc[n], ahi, b.z, b.w);
                mma_bf16(acc[n], alo, b.x, b.y);
            }
        }

        float* rb = red + (t & 1) * RED_FLOATS;
#pragma unroll
        for (int n = 0; n < 4; ++n) {
            *(float4*)(rb + (size_t)(((w * 4 + n) * 32 + lane)) * 4) = acc[n];
        }
        __syncthreads();

        if (tid < 128) {
            float gi = xgi + bi, gf = xgf + bf_, gg = xgg + bgt, go = xgo + bo;
#pragma unroll
            for (int q = 0; q < 8; ++q) {
                const float* rp = rb + (size_t)(q * 4) * 128;
                gi += rp[lane_c * 4 + reg_c];
                gf += rp[128 + lane_c * 4 + reg_c];
                gg += rp[256 + lane_c * 4 + reg_c];
                go += rp[384 + lane_c * 4 + reg_c];
            }
            float iv = fast_sigmoid(gi);
            float fv = fast_sigmoid(gf);
            float gv = fast_tanh(gg);
            float ov = fast_sigmoid(go);
            c_reg    = fv * c_reg + iv * gv;
            float hv = ov * fast_tanh(c_reg);
            h_last   = hv;

            // publish FIRST (inter-block critical path), then dout
            if (t + 1 < TT) {
                __nv_bfloat16 hhi, hlo;
                split_bf16(hv, hhi, hlo);
                uint32_t v  = pack_bf2(hhi, hlo);
                uint32_t pv = __shfl_xor_sync(0xffffffffu, v, 1);
                if (even) {
                    uint2 pr;
                    pr.x = (v & 0xffffu) | ((pv & 0xffffu) << 16);
                    pr.y = (v >> 16) | ((pv >> 16) << 16);
                    *(uint2*)(g_hfrag[(t + 1) & 1] + whoff) = pr;
                }
                asm volatile("bar.sync 1, 128;" ::: "memory");
                if (tid == 0) {
                    asm volatile("red.release.gpu.global.add.u32 [%0], %1;"
                                 :: "l"(&g_flags[myflag * 64]), "r"(1u)
                                 : "memory");
                }
            }
            dout[((size_t)pb * TT + t) * DD + pdg] = hv;
        }
    }

    if (tid < 128) {
        nc[((size_t)pb * DD + pdg) * 2 + 0] = h_last;
        nc[((size_t)pb * DD + pdg) * 2 + 1] = c_reg;
    }

    __syncthreads();
    if (tid == 0) {
        __threadfence();
        unsigned r = atomicAdd(&g_endcnt, 1u);
        if ((r & 127u) == 127u) {
            for (int g = 0; g < 64; ++g) g_flags[g * 64] = 0u;
            __threadfence();
        }
    }
}

// ---------------------------------------------------------------------------
// Launch
// ---------------------------------------------------------------------------
extern "C" void kernel_launch(void* const* d_in, const int* in_sizes, int n_in,
                              void* d_out, int out_size) {
    (void)in_sizes; (void)n_in; (void)out_size;
    const float* x     = (const float*)d_in[0];
    const float* carry = (const float*)d_in[1];
    const float* Wi    = (const float*)d_in[2];
    const float* Wh    = (const float*)d_in[3];
    const float* b     = (const float*)d_in[4];
    float* out = (float*)d_out;

    {
        __nv_bfloat16 *xhi, *xlo, *wihi, *wilo;
        cudaGetSymbolAddress((void**)&xhi,  g_xhi);
        cudaGetSymbolAddress((void**)&xlo,  g_xlo);
        cudaGetSymbolAddress((void**)&wihi, g_wihi);
        cudaGetSymbolAddress((void**)&wilo, g_wilo);
        size_t nx4 = (size_t)BB * TT * DD / 4;
        size_t nw4 = (size_t)DD * EE / 4;
        split_kernel<<<(unsigned)((nx4 + 255) / 256), 256>>>(x, xhi, xlo, nx4);
        split_kernel<<<(unsigned)((nw4 + 255) / 256), 256>>>(Wi, wihi, wilo, nw4);
    }

    cudaFuncSetAttribute(gemm_xg_mma,
                         cudaFuncAttributeMaxDynamicSharedMemorySize,
                         GEMM_SMEM_BYTES);
    dim3 ggrid(EE / 128, (BB * TT) / 128);
    gemm_xg_mma<<<ggrid, 256, GEMM_SMEM_BYTES>>>();

    cudaFuncSetAttribute(lstm_rec_kernel,
                         cudaFuncAttributeMaxDynamicSharedMemorySize,
                         REC_SMEM_BYTES);
    lstm_rec_kernel<<<REC_BLOCKS, 256, REC_SMEM_BYTES>>>(carry, Wh, b, out);
}

// round 15
// speedup vs baseline: 1.9950x; 1.9950x over previous
#include <cuda_runtime.h>
#include <cuda_bf16.h>
#include <cstdint>
#include <cstddef>

// Problem constants: B=16, T=2048, D=1024, E=4D=4096
#define BB 16
#define TT 2048
#define DD 1024
#define EE 4096

#define REC_BLOCKS 128
#define DPB (DD / REC_BLOCKS)

// ---------------------------------------------------------------------------
// Device scratch
// ---------------------------------------------------------------------------
__device__ float g_xg[(size_t)BB * TT * EE];

__device__ __nv_bfloat16 g_xhi[(size_t)BB * TT * DD];
__device__ __nv_bfloat16 g_xlo[(size_t)BB * TT * DD];
__device__ __nv_bfloat16 g_wihi[(size_t)DD * EE];
__device__ __nv_bfloat16 g_wilo[(size_t)DD * EE];

// h in mma A-fragment order, hi/lo interleaved per register.
__device__ __align__(16) uint32_t g_hfrag[2][64 * 32 * 8];

// R5-proven flag scheme: one counter per k-group (warp 0..7), 256 B apart.
__device__ unsigned g_flags[8 * 64];
__device__ unsigned g_endcnt;

// ---------------------------------------------------------------------------
// Helpers
// ---------------------------------------------------------------------------
__device__ __forceinline__ void mma4(float* c, const uint32_t* a,
                                     uint32_t b0, uint32_t b1) {
    asm volatile(
        "mma.sync.aligned.m16n8k16.row.col.f32.bf16.bf16.f32 "
        "{%0,%1,%2,%3}, {%4,%5,%6,%7}, {%8,%9}, {%0,%1,%2,%3};\n"
        : "+f"(c[0]), "+f"(c[1]), "+f"(c[2]), "+f"(c[3])
        : "r"(a[0]), "r"(a[1]), "r"(a[2]), "r"(a[3]), "r"(b0), "r"(b1));
}

__device__ __forceinline__ void mma_bf16(float4& c, const uint4& a,
                                         uint32_t b0, uint32_t b1) {
    asm volatile(
        "mma.sync.aligned.m16n8k16.row.col.f32.bf16.bf16.f32 "
        "{%0,%1,%2,%3}, {%4,%5,%6,%7}, {%8,%9}, {%0,%1,%2,%3};\n"
        : "+f"(c.x), "+f"(c.y), "+f"(c.z), "+f"(c.w)
        : "r"(a.x), "r"(a.y), "r"(a.z), "r"(a.w), "r"(b0), "r"(b1));
}

__device__ __forceinline__ void ldsm_x4(uint32_t* r, uint32_t addr) {
    asm volatile("ldmatrix.sync.aligned.m8n8.x4.shared.b16 {%0,%1,%2,%3}, [%4];"
        : "=r"(r[0]), "=r"(r[1]), "=r"(r[2]), "=r"(r[3]) : "r"(addr));
}
__device__ __forceinline__ void ldsm_x4_t(uint32_t* r, uint32_t addr) {
    asm volatile("ldmatrix.sync.aligned.m8n8.x4.trans.shared.b16 {%0,%1,%2,%3}, [%4];"
        : "=r"(r[0]), "=r"(r[1]), "=r"(r[2]), "=r"(r[3]) : "r"(addr));
}

__device__ __forceinline__ void split_bf16(float v, __nv_bfloat16& hi,
                                           __nv_bfloat16& lo) {
    hi = __float2bfloat16(v);
    lo = __float2bfloat16(v - __bfloat162float(hi));
}

__device__ __forceinline__ uint32_t pack_bf2(__nv_bfloat16 a, __nv_bfloat16 b) {
    return (uint32_t)__bfloat16_as_ushort(a) |
           ((uint32_t)__bfloat16_as_ushort(b) << 16);
}

__device__ __forceinline__ float fast_sigmoid(float x) {
    return __fdividef(1.f, 1.f + __expf(-x));
}
__device__ __forceinline__ float fast_tanh(float x) {
    return __fdividef(2.f, 1.f + __expf(-2.f * x)) - 1.f;
}

#define CP_ASYNC16(dst, src) \
    asm volatile("cp.async.cg.shared.global [%0], [%1], 16;" \
                 :: "r"(dst), "l"(src))
#define CP_COMMIT() asm volatile("cp.async.commit_group;" ::: "memory")
#define CP_WAIT1()  asm volatile("cp.async.wait_group 1;" ::: "memory")
#define CP_WAIT0()  asm volatile("cp.async.wait_group 0;" ::: "memory")

// ---------------------------------------------------------------------------
// Phase 0: split fp32 -> bf16 hi/lo planes
// ---------------------------------------------------------------------------
__global__ __launch_bounds__(256) void split_kernel(
    const float* __restrict__ src,
    __nv_bfloat16* __restrict__ hi,
    __nv_bfloat16* __restrict__ lo,
    size_t n4)
{
    size_t i = (size_t)blockIdx.x * 256 + threadIdx.x;
    if (i >= n4) return;
    float4 v = ((const float4*)src)[i];
    __nv_bfloat16 h[4], l[4];
    split_bf16(v.x, h[0], l[0]);
    split_bf16(v.y, h[1], l[1]);
    split_bf16(v.z, h[2], l[2]);
    split_bf16(v.w, h[3], l[3]);
    ((uint2*)hi)[i] = make_uint2(pack_bf2(h[0], h[1]), pack_bf2(h[2], h[3]));
    ((uint2*)lo)[i] = make_uint2(pack_bf2(l[0], l[1]), pack_bf2(l[2], l[3]));
}

// ---------------------------------------------------------------------------
// Phase 1: xg = x @ Wi — 3-pass bf16 MMA, 2-stage cp.async, 2 blocks/SM.
// ---------------------------------------------------------------------------
#define A_STRIDE 40
#define B_STRIDE 136
#define A_PLANE (128 * A_STRIDE)
#define B_PLANE (32 * B_STRIDE)
#define STAGE_ELEMS (2 * A_PLANE + 2 * B_PLANE)
#define STAGE_BYTES (STAGE_ELEMS * 2)
#define GEMM_SMEM_BYTES (2 * STAGE_BYTES)       // 75776 -> 2 blocks/SM

__global__ __launch_bounds__(256, 2) void gemm_xg_mma(void)
{
    extern __shared__ __align__(16) __nv_bfloat16 gsm[];

    const int tid  = threadIdx.x;
    const int lane = tid & 31;
    const int w    = tid >> 5;
    const int wn   = w >> 2;
    const int wm   = w & 3;
    const int m0   = blockIdx.y * 128;
    const int n0   = blockIdx.x * 128;

    const uint32_t smem_u32 = (uint32_t)__cvta_generic_to_shared(gsm);

    auto issue_stage = [&](int stage, int kt) {
        const int k0 = kt * 32;
        uint32_t sb = smem_u32 + stage * STAGE_BYTES;
#pragma unroll
        for (int r = 0; r < 2; ++r) {
            int chunk = tid + 256 * r;
            int row   = chunk >> 2;
            int c8    = (chunk & 3) * 8;
            const __nv_bfloat16* sh = g_xhi + (size_t)(m0 + row) * DD + k0 + c8;
            const __nv_bfloat16* sl = g_xlo + (size_t)(m0 + row) * DD + k0 + c8;
            uint32_t dh = sb + (uint32_t)(row * A_STRIDE + c8) * 2;
            uint32_t dl = dh + A_PLANE * 2;
            CP_ASYNC16(dh, sh);
            CP_ASYNC16(dl, sl);
        }
        uint32_t bb = sb + 4 * A_PLANE;
#pragma unroll
        for (int r = 0; r < 2; ++r) {
            int chunk = tid + 256 * r;
            int row   = chunk >> 4;
            int c8    = (chunk & 15) * 8;
            const __nv_bfloat16* sh = g_wihi + (size_t)(k0 + row) * EE + n0 + c8;
            const __nv_bfloat16* sl = g_wilo + (size_t)(k0 + row) * EE + n0 + c8;
            uint32_t dh = bb + (uint32_t)(row * B_STRIDE + c8) * 2;
            uint32_t dl = dh + B_PLANE * 2;
            CP_ASYNC16(dh, sh);
            CP_ASYNC16(dl, sl);
        }
    };

    float acc[2][8][4];
#pragma unroll
    for (int mt = 0; mt < 2; ++mt)
#pragma unroll
        for (int nt = 0; nt < 8; ++nt)
#pragma unroll
            for (int i = 0; i < 4; ++i) acc[mt][nt][i] = 0.f;

    issue_stage(0, 0); CP_COMMIT();
    issue_stage(1, 1); CP_COMMIT();

    for (int it = 0; it < 32; ++it) {
        if (it < 31) CP_WAIT1(); else CP_WAIT0();
        __syncthreads();

        const int stage = it & 1;
        const uint32_t aBase = smem_u32 + stage * STAGE_BYTES;
        const uint32_t bBase = aBase + 4 * A_PLANE;

#pragma unroll
        for (int ks = 0; ks < 2; ++ks) {
            uint32_t afr[2][2][4];
#pragma unroll
            for (int mt = 0; mt < 2; ++mt)
#pragma unroll
                for (int p = 0; p < 2; ++p) {
                    uint32_t addr = aBase + p * (A_PLANE * 2)
                        + (uint32_t)((wm * 32 + mt * 16 + (lane & 15)) * (A_STRIDE * 2))
                        + (uint32_t)((ks * 16 + (lane >> 4) * 8) * 2);
                    ldsm_x4(afr[mt][p], addr);
                }
            uint32_t bfr[4][2][4];
#pragma unroll
            for (int np = 0; np < 4; ++np)
#pragma unroll
                for (int p = 0; p < 2; ++p) {
                    uint32_t addr = bBase + p * (B_PLANE * 2)
                        + (uint32_t)((ks * 16 + (lane & 15)) * (B_STRIDE * 2))
                        + (uint32_t)((wn * 64 + np * 16 + (lane >> 4) * 8) * 2);
                    ldsm_x4_t(bfr[np][p], addr);
                }
#pragma unroll
            for (int mt = 0; mt < 2; ++mt)
#pragma unroll
                for (int np = 0; np < 4; ++np)
#pragma unroll
                    for (int hf = 0; hf < 2; ++hf) {
                        int nt = np * 2 + hf;
                        float* c = acc[mt][nt];
                        uint32_t bh0 = bfr[np][0][hf * 2];
                        uint32_t bh1 = bfr[np][0][hf * 2 + 1];
                        uint32_t bl0 = bfr[np][1][hf * 2];
                        uint32_t bl1 = bfr[np][1][hf * 2 + 1];
                        mma4(c, afr[mt][0], bh0, bh1);
                        mma4(c, afr[mt][0], bl0, bl1);
                        mma4(c, afr[mt][1], bh0, bh1);
                    }
        }
        __syncthreads();     // whole block done reading stage before refill
        if (it + 2 < 32) issue_stage(stage, it + 2);
        CP_COMMIT();
    }

#pragma unroll
    for (int mt = 0; mt < 2; ++mt)
#pragma unroll
        for (int nt = 0; nt < 8; ++nt) {
            int row = m0 + wm * 32 + mt * 16 + (lane >> 2);
            int col = n0 + wn * 64 + nt * 8 + (lane & 3) * 2;
            float* c = acc[mt][nt];
            __stcs((float2*)(g_xg + (size_t)row * EE + col),
                   make_float2(c[0], c[1]));
            __stcs((float2*)(g_xg + (size_t)(row + 8) * EE + col),
                   make_float2(c[2], c[3]));
        }
}

// ---------------------------------------------------------------------------
// Phase 2: persistent recurrence — EXACT R5 structure (frozen).
// ---------------------------------------------------------------------------
#define W_WORDS (4 * 64 * 32 * 4)
#define RED_FLOATS (8 * 4 * 32 * 4)
#define REC_SMEM_BYTES (W_WORDS * 4 + 2 * RED_FLOATS * 4)

__global__ __launch_bounds__(256, 1) void lstm_rec_kernel(
    const float* __restrict__ carry,
    const float* __restrict__ Wh,
    const float* __restrict__ bias,
    float* __restrict__ dout)
{
    extern __shared__ uint32_t sm_w[];
    float* red = (float*)(sm_w + W_WORDS);

    const int tid  = threadIdx.x;
    const int w    = tid >> 5;
    const int lane = tid & 31;
    const int d0   = blockIdx.x * DPB;

    for (int idx = tid; idx < 4 * 64 * 32 * 2; idx += 256) {
        int n    = idx >> 12;
        int rem  = idx & 4095;
        int ks   = rem >> 6;
        int rem2 = rem & 63;
        int ln   = rem2 >> 1;
        int reg  = rem2 & 1;
        int tig  = ln & 3;
        int dl   = ln >> 2;
        int kb   = ks * 16 + reg * 8 + tig * 2;
        size_t col = (size_t)n * DD + d0 + dl;
        float v0 = Wh[(size_t)kb * EE + col];
        float v1 = Wh[(size_t)(kb + 1) * EE + col];
        __nv_bfloat16 h0, l0, h1, l1;
        split_bf16(v0, h0, l0);
        split_bf16(v1, h1, l1);
        uint32_t* wp = sm_w + (size_t)(((n * 64 + ks) * 32 + ln)) * 4;
        wp[reg]     = pack_bf2(h0, h1);
        wp[2 + reg] = pack_bf2(l0, l1);
    }

    float c_reg = 0.f, h_last = 0.f, bi = 0.f, bf_ = 0.f, bgt = 0.f, bo = 0.f;
    int pb = 0, pd = 0, pdg = 0, lane_c = 0, reg_c = 0;
    unsigned whoff = 0;
    int even = 0;
    unsigned myflag = (unsigned)(blockIdx.x >> 4);

    if (tid < 128) {
        pd  = tid & 7;
        pb  = tid >> 3;
        pdg = d0 + pd;
        int ksp  = pdg >> 4;
        int cc   = pdg & 15;
        int lnp  = (pb & 7) * 4 + ((cc & 7) >> 1);
        int regp = ((pb >> 3) & 1) + 2 * ((cc >> 3) & 1);
        whoff = (unsigned)((ksp * 32 + lnp) * 8 + 2 * regp);
        even  = ((cc & 1) == 0);
        lane_c = (pb & 7) * 4 + (pd >> 1);
        reg_c  = 2 * (pb >> 3) + (pd & 1);

        c_reg = carry[((size_t)pb * DD + pdg) * 2 + 1];
        float h0v = carry[((size_t)pb * DD + pdg) * 2 + 0];
        bi  = bias[pdg];
        bf_ = bias[DD + pdg];
        bgt = bias[2 * DD + pdg];
        bo  = bias[3 * DD + pdg];

        __nv_bfloat16 hhi, hlo;
        split_bf16(h0v, hhi, hlo);
        uint32_t v  = pack_bf2(hhi, hlo);
        uint32_t pv = __shfl_xor_sync(0xffffffffu, v, 1);
        if (even) {
            uint2 pr;
            pr.x = (v & 0xffffu) | ((pv & 0xffffu) << 16);
            pr.y = (v >> 16) | ((pv >> 16) << 16);
            *(uint2*)(g_hfrag[0] + whoff) = pr;
        }
    }
    __syncthreads();
    if (tid == 0) {
        asm volatile("red.release.gpu.global.add.u32 [%0], %1;"
                     :: "l"(&g_flags[myflag * 64]), "r"(1u) : "memory");
    }

    unsigned* const fp = &g_flags[(unsigned)w * 64];
    float* nc = dout + (size_t)BB * TT * DD;

    for (int t = 0; t < TT; ++t) {
        float xgi = 0.f, xgf = 0.f, xgg = 0.f, xgo = 0.f;
        if (tid < 128) {
            const float* xr = g_xg + ((size_t)pb * TT + t) * EE + pdg;
            xgi = __ldg(xr);
            xgf = __ldg(xr + DD);
            xgg = __ldg(xr + 2 * DD);
            xgo = __ldg(xr + 3 * DD);
        }

        {
            const unsigned tgt = (unsigned)(t + 1) * 16u;
            unsigned v;
            do {
                asm volatile("ld.global.acquire.gpu.u32 %0, [%1];"
                             : "=r"(v) : "l"(fp) : "memory");
            } while (v < tgt);
        }

        float4 acc[4];
#pragma unroll
        for (int n = 0; n < 4; ++n) acc[n] = make_float4(0.f, 0.f, 0.f, 0.f);

        const uint4* ab = (const uint4*)g_hfrag[t & 1];
#pragma unroll
        for (int j = 0; j < 8; ++j) {
            int ks = w * 8 + j;
            uint4 q0 = __ldcg(ab + (ks * 32 + lane) * 2);
            uint4 q1 = __ldcg(ab + (ks * 32 + lane) * 2 + 1);
            uint4 ahi = make_uint4(q0.x, q0.z, q1.x, q1.z);
            uint4 alo = make_uint4(q0.y, q0.w, q1.y, q1.w);
#pragma unroll
            for (int n = 0; n < 4; ++n) {
                uint4 b = *(const uint4*)(sm_w + (size_t)(((n * 64 + ks) * 32 + lane)) * 4);
                mma_bf16(acc[n], ahi, b.x, b.y);
                mma_bf16(acc[n], ahi, b.z, b.w);
                mma_bf16(acc[n], alo, b.x, b.y);
            }
        }

        float* rb = red + (t & 1) * RED_FLOATS;
#pragma unroll
        for (int n = 0; n < 4; ++n) {
            *(float4*)(rb + (size_t)(((w * 4 + n) * 32 + lane)) * 4) = acc[n];
        }
        __syncthreads();

        if (tid < 128) {
            float gi = xgi + bi, gf = xgf + bf_, gg = xgg + bgt, go = xgo + bo;
#pragma unroll
            for (int q = 0; q < 8; ++q) {
                const float* rp = rb + (size_t)(q * 4) * 128;
                gi += rp[lane_c * 4 + reg_c];
                gf += rp[128 + lane_c * 4 + reg_c];
                gg += rp[256 + lane_c * 4 + reg_c];
                go += rp[384 + lane_c * 4 + reg_c];
            }
            float iv = fast_sigmoid(gi);
            float fv = fast_sigmoid(gf);
            float gv = fast_tanh(gg);
            float ov = fast_sigmoid(go);
            c_reg    = fv * c_reg + iv * gv;
            float hv = ov * fast_tanh(c_reg);
            h_last   = hv;

            if (t + 1 < TT) {
                __nv_bfloat16 hhi, hlo;
                split_bf16(hv, hhi, hlo);
                uint32_t v  = pack_bf2(hhi, hlo);
                uint32_t pv = __shfl_xor_sync(0xffffffffu, v, 1);
                if (even) {
                    uint2 pr;
                    pr.x = (v & 0xffffu) | ((pv & 0xffffu) << 16);
                    pr.y = (v >> 16) | ((pv >> 16) << 16);
                    *(uint2*)(g_hfrag[(t + 1) & 1] + whoff) = pr;
                }
                asm volatile("bar.sync 1, 128;" ::: "memory");
                if (tid == 0) {
                    asm volatile("red.release.gpu.global.add.u32 [%0], %1;"
                                 :: "l"(&g_flags[myflag * 64]), "r"(1u)
                                 : "memory");
                }
            }
            dout[((size_t)pb * TT + t) * DD + pdg] = hv;
        }
    }

    if (tid < 128) {
        nc[((size_t)pb * DD + pdg) * 2 + 0] = h_last;
        nc[((size_t)pb * DD + pdg) * 2 + 1] = c_reg;
    }

    __syncthreads();
    if (tid == 0) {
        __threadfence();
        unsigned r = atomicAdd(&g_endcnt, 1u);
        if ((r & 127u) == 127u) {
#pragma unroll
            for (int g = 0; g < 8; ++g) g_flags[g * 64] = 0u;
            __threadfence();
        }
    }
}

// ---------------------------------------------------------------------------
// Launch
// ---------------------------------------------------------------------------
extern "C" void kernel_launch(void* const* d_in, const int* in_sizes, int n_in,
                              void* d_out, int out_size) {
    (void)in_sizes; (void)n_in; (void)out_size;
    const float* x     = (const float*)d_in[0];
    const float* carry = (const float*)d_in[1];
    const float* Wi    = (const float*)d_in[2];
    const float* Wh    = (const float*)d_in[3];
    const float* b     = (const float*)d_in[4];
    float* out = (float*)d_out;

    {
        __nv_bfloat16 *xhi, *xlo, *wihi, *wilo;
        cudaGetSymbolAddress((void**)&xhi,  g_xhi);
        cudaGetSymbolAddress((void**)&xlo,  g_xlo);
        cudaGetSymbolAddress((void**)&wihi, g_wihi);
        cudaGetSymbolAddress((void**)&wilo, g_wilo);
        size_t nx4 = (size_t)BB * TT * DD / 4;
        size_t nw4 = (size_t)DD * EE / 4;
        split_kernel<<<(unsigned)((nx4 + 255) / 256), 256>>>(x, xhi, xlo, nx4);
        split_kernel<<<(unsigned)((nw4 + 255) / 256), 256>>>(Wi, wihi, wilo, nw4);
    }

    cudaFuncSetAttribute(gemm_xg_mma,
                         cudaFuncAttributeMaxDynamicSharedMemorySize,
                         GEMM_SMEM_BYTES);
    dim3 ggrid(EE / 128, (BB * TT) / 128);
    gemm_xg_mma<<<ggrid, 256, GEMM_SMEM_BYTES>>>();

    cudaFuncSetAttribute(lstm_rec_kernel,
                         cudaFuncAttributeMaxDynamicSharedMemorySize,
                         REC_SMEM_BYTES);
    lstm_rec_kernel<<<REC_BLOCKS, 256, REC_SMEM_BYTES>>>(carry, Wh, b, out);
}

// round 16
// speedup vs baseline: 2.1642x; 1.0848x over previous
#include <cuda_runtime.h>
#include <cuda_bf16.h>
#include <cuda_fp16.h>
#include <cstdint>
#include <cstddef>

// Problem constants: B=16, T=2048, D=1024, E=4D=4096
#define BB 16
#define TT 2048
#define DD 1024
#define EE 4096

#define REC_BLOCKS 128
#define DPB (DD / REC_BLOCKS)

// ---------------------------------------------------------------------------
// Device scratch
// ---------------------------------------------------------------------------
__device__ float g_xg[(size_t)BB * TT * EE];

__device__ __half g_xh[(size_t)BB * TT * DD];      // x hi (fp16)
__device__ __half g_wihi[(size_t)DD * EE];         // Wi hi (fp16)
__device__ __half g_wilo[(size_t)DD * EE];         // Wi lo (fp16)

// h in mma A-fragment order, hi/lo interleaved per register (bf16, rec only).
__device__ __align__(16) uint32_t g_hfrag[2][64 * 32 * 8];

// R5-proven flag scheme: one counter per k-group (warp 0..7), 256 B apart.
__device__ unsigned g_flags[8 * 64];
__device__ unsigned g_endcnt;

// ---------------------------------------------------------------------------
// Helpers
// ---------------------------------------------------------------------------
__device__ __forceinline__ void mma4_f16(float* c, const uint32_t* a,
                                         uint32_t b0, uint32_t b1) {
    asm volatile(
        "mma.sync.aligned.m16n8k16.row.col.f32.f16.f16.f32 "
        "{%0,%1,%2,%3}, {%4,%5,%6,%7}, {%8,%9}, {%0,%1,%2,%3};\n"
        : "+f"(c[0]), "+f"(c[1]), "+f"(c[2]), "+f"(c[3])
        : "r"(a[0]), "r"(a[1]), "r"(a[2]), "r"(a[3]), "r"(b0), "r"(b1));
}

__device__ __forceinline__ void mma_bf16(float4& c, const uint4& a,
                                         uint32_t b0, uint32_t b1) {
    asm volatile(
        "mma.sync.aligned.m16n8k16.row.col.f32.bf16.bf16.f32 "
        "{%0,%1,%2,%3}, {%4,%5,%6,%7}, {%8,%9}, {%0,%1,%2,%3};\n"
        : "+f"(c.x), "+f"(c.y), "+f"(c.z), "+f"(c.w)
        : "r"(a.x), "r"(a.y), "r"(a.z), "r"(a.w), "r"(b0), "r"(b1));
}

__device__ __forceinline__ void ldsm_x4(uint32_t* r, uint32_t addr) {
    asm volatile("ldmatrix.sync.aligned.m8n8.x4.shared.b16 {%0,%1,%2,%3}, [%4];"
        : "=r"(r[0]), "=r"(r[1]), "=r"(r[2]), "=r"(r[3]) : "r"(addr));
}
__device__ __forceinline__ void ldsm_x4_t(uint32_t* r, uint32_t addr) {
    asm volatile("ldmatrix.sync.aligned.m8n8.x4.trans.shared.b16 {%0,%1,%2,%3}, [%4];"
        : "=r"(r[0]), "=r"(r[1]), "=r"(r[2]), "=r"(r[3]) : "r"(addr));
}

__device__ __forceinline__ void split_bf16(float v, __nv_bfloat16& hi,
                                           __nv_bfloat16& lo) {
    hi = __float2bfloat16(v);
    lo = __float2bfloat16(v - __bfloat162float(hi));
}

__device__ __forceinline__ void split_f16(float v, __half& hi, __half& lo) {
    hi = __float2half_rn(v);
    lo = __float2half_rn(v - __half2float(hi));
}

__device__ __forceinline__ uint32_t pack_bf2(__nv_bfloat16 a, __nv_bfloat16 b) {
    return (uint32_t)__bfloat16_as_ushort(a) |
           ((uint32_t)__bfloat16_as_ushort(b) << 16);
}
__device__ __forceinline__ uint32_t pack_h2(__half a, __half b) {
    return (uint32_t)__half_as_ushort(a) |
           ((uint32_t)__half_as_ushort(b) << 16);
}

__device__ __forceinline__ float fast_sigmoid(float x) {
    return __fdividef(1.f, 1.f + __expf(-x));
}
__device__ __forceinline__ float fast_tanh(float x) {
    return __fdividef(2.f, 1.f + __expf(-2.f * x)) - 1.f;
}

#define CP_ASYNC16(dst, src) \
    asm volatile("cp.async.cg.shared.global [%0], [%1], 16;" \
                 :: "r"(dst), "l"(src))
#define CP_COMMIT() asm volatile("cp.async.commit_group;" ::: "memory")
#define CP_WAIT2()  asm volatile("cp.async.wait_group 2;" ::: "memory")

// ---------------------------------------------------------------------------
// Phase 0a: x fp32 -> fp16 hi plane only
// ---------------------------------------------------------------------------
__global__ __launch_bounds__(256) void convert_x(
    const float* __restrict__ src, size_t n4)
{
    size_t i = (size_t)blockIdx.x * 256 + threadIdx.x;
    if (i >= n4) return;
    float4 v = ((const float4*)src)[i];
    uint2 o;
    o.x = pack_h2(__float2half_rn(v.x), __float2half_rn(v.y));
    o.y = pack_h2(__float2half_rn(v.z), __float2half_rn(v.w));
    ((uint2*)g_xh)[i] = o;
}

// ---------------------------------------------------------------------------
// Phase 0b: Wi fp32 -> fp16 hi/lo planes
// ---------------------------------------------------------------------------
__global__ __launch_bounds__(256) void split_wi(
    const float* __restrict__ src, size_t n4)
{
    size_t i = (size_t)blockIdx.x * 256 + threadIdx.x;
    if (i >= n4) return;
    float4 v = ((const float4*)src)[i];
    __half h[4], l[4];
    split_f16(v.x, h[0], l[0]);
    split_f16(v.y, h[1], l[1]);
    split_f16(v.z, h[2], l[2]);
    split_f16(v.w, h[3], l[3]);
    ((uint2*)g_wihi)[i] = make_uint2(pack_h2(h[0], h[1]), pack_h2(h[2], h[3]));
    ((uint2*)g_wilo)[i] = make_uint2(pack_h2(l[0], l[1]), pack_h2(l[2], l[3]));
}

// ---------------------------------------------------------------------------
// Phase 1: xg = x @ Wi — fp16 2-pass MMA (a_hi*b_hi + a_hi*b_lo),
// cp.async 3-stage pipeline.  BM=128, BN=128, BK=32, warp tile 32x64.
// ---------------------------------------------------------------------------
#define A_STRIDE 40          // fp16 elems per A row (32 + 8 pad)
#define B_STRIDE 136         // fp16 elems per B k-row (128 + 8 pad)
#define A_PLANE (128 * A_STRIDE)
#define B_PLANE (32 * B_STRIDE)
#define STAGE_ELEMS (A_PLANE + 2 * B_PLANE)
#define STAGE_BYTES (STAGE_ELEMS * 2)         // 27648
#define GEMM_SMEM_BYTES (3 * STAGE_BYTES)     // 82944

__global__ __launch_bounds__(256) void gemm_xg_mma(void)
{
    extern __shared__ __align__(16) __half gsm[];

    const int tid  = threadIdx.x;
    const int lane = tid & 31;
    const int w    = tid >> 5;
    const int wn   = w >> 2;
    const int wm   = w & 3;
    const int m0   = blockIdx.y * 128;
    const int n0   = blockIdx.x * 128;

    const uint32_t smem_u32 = (uint32_t)__cvta_generic_to_shared(gsm);

    auto issue_stage = [&](int stage, int kt) {
        const int k0 = kt * 32;
        uint32_t sb = smem_u32 + stage * STAGE_BYTES;
        // A hi plane: 512 chunks of 16B
#pragma unroll
        for (int r = 0; r < 2; ++r) {
            int chunk = tid + 256 * r;
            int row   = chunk >> 2;
            int c8    = (chunk & 3) * 8;
            const __half* sh = g_xh + (size_t)(m0 + row) * DD + k0 + c8;
            CP_ASYNC16(sb + (uint32_t)(row * A_STRIDE + c8) * 2, sh);
        }
        // B hi/lo planes: 512 chunks each
        uint32_t bb = sb + 2 * A_PLANE;       // bytes
#pragma unroll
        for (int r = 0; r < 2; ++r) {
            int chunk = tid + 256 * r;
            int row   = chunk >> 4;
            int c8    = (chunk & 15) * 8;
            const __half* sh = g_wihi + (size_t)(k0 + row) * EE + n0 + c8;
            const __half* sl = g_wilo + (size_t)(k0 + row) * EE + n0 + c8;
            uint32_t dh = bb + (uint32_t)(row * B_STRIDE + c8) * 2;
            uint32_t dl = dh + B_PLANE * 2;
            CP_ASYNC16(dh, sh);
            CP_ASYNC16(dl, sl);
        }
    };

    float acc[2][8][4];
#pragma unroll
    for (int mt = 0; mt < 2; ++mt)
#pragma unroll
        for (int nt = 0; nt < 8; ++nt)
#pragma unroll
            for (int i = 0; i < 4; ++i) acc[mt][nt][i] = 0.f;

    issue_stage(0, 0); CP_COMMIT();
    issue_stage(1, 1); CP_COMMIT();
    issue_stage(2, 2); CP_COMMIT();

    for (int it = 0; it < 32; ++it) {
        CP_WAIT2();
        __syncthreads();

        const int stage = it % 3;
        const uint32_t aBase = smem_u32 + stage * STAGE_BYTES;
        const uint32_t bBase = aBase + 2 * A_PLANE;

#pragma unroll
        for (int ks = 0; ks < 2; ++ks) {
            uint32_t afr[2][4];
#pragma unroll
            for (int mt = 0; mt < 2; ++mt) {
                uint32_t addr = aBase
                    + (uint32_t)((wm * 32 + mt * 16 + (lane & 15)) * (A_STRIDE * 2))
                    + (uint32_t)((ks * 16 + (lane >> 4) * 8) * 2);
                ldsm_x4(afr[mt], addr);
            }
            uint32_t bfr[4][2][4];
#pragma unroll
            for (int np = 0; np < 4; ++np)
#pragma unroll
                for (int p = 0; p < 2; ++p) {
                    uint32_t addr = bBase + p * (B_PLANE * 2)
                        + (uint32_t)((ks * 16 + (lane & 15)) * (B_STRIDE * 2))
                        + (uint32_t)((wn * 64 + np * 16 + (lane >> 4) * 8) * 2);
                    ldsm_x4_t(bfr[np][p], addr);
                }
#pragma unroll
            for (int mt = 0; mt < 2; ++mt)
#pragma unroll
                for (int np = 0; np < 4; ++np)
#pragma unroll
                    for (int hf = 0; hf < 2; ++hf) {
                        int nt = np * 2 + hf;
                        float* c = acc[mt][nt];
                        mma4_f16(c, afr[mt], bfr[np][0][hf * 2],
                                 bfr[np][0][hf * 2 + 1]);     // hi*hi
                        mma4_f16(c, afr[mt], bfr[np][1][hf * 2],
                                 bfr[np][1][hf * 2 + 1]);     // hi*lo
                    }
        }
        __syncthreads();
        if (it + 3 < 32) issue_stage(stage, it + 3);
        CP_COMMIT();
    }

#pragma unroll
    for (int mt = 0; mt < 2; ++mt)
#pragma unroll
        for (int nt = 0; nt < 8; ++nt) {
            int row = m0 + wm * 32 + mt * 16 + (lane >> 2);
            int col = n0 + wn * 64 + nt * 8 + (lane & 3) * 2;
            float* c = acc[mt][nt];
            __stcs((float2*)(g_xg + (size_t)row * EE + col),
                   make_float2(c[0], c[1]));
            __stcs((float2*)(g_xg + (size_t)(row + 8) * EE + col),
                   make_float2(c[2], c[3]));
        }
}

// ---------------------------------------------------------------------------
// Phase 2: persistent recurrence — EXACT R5 structure (frozen).
// ---------------------------------------------------------------------------
#define W_WORDS (4 * 64 * 32 * 4)
#define RED_FLOATS (8 * 4 * 32 * 4)
#define REC_SMEM_BYTES (W_WORDS * 4 + 2 * RED_FLOATS * 4)

__global__ __launch_bounds__(256, 1) void lstm_rec_kernel(
    const float* __restrict__ carry,
    const float* __restrict__ Wh,
    const float* __restrict__ bias,
    float* __restrict__ dout)
{
    extern __shared__ uint32_t sm_w[];
    float* red = (float*)(sm_w + W_WORDS);

    const int tid  = threadIdx.x;
    const int w    = tid >> 5;
    const int lane = tid & 31;
    const int d0   = blockIdx.x * DPB;

    for (int idx = tid; idx < 4 * 64 * 32 * 2; idx += 256) {
        int n    = idx >> 12;
        int rem  = idx & 4095;
        int ks   = rem >> 6;
        int rem2 = rem & 63;
        int ln   = rem2 >> 1;
        int reg  = rem2 & 1;
        int tig  = ln & 3;
        int dl   = ln >> 2;
        int kb   = ks * 16 + reg * 8 + tig * 2;
        size_t col = (size_t)n * DD + d0 + dl;
        float v0 = Wh[(size_t)kb * EE + col];
        float v1 = Wh[(size_t)(kb + 1) * EE + col];
        __nv_bfloat16 h0, l0, h1, l1;
        split_bf16(v0, h0, l0);
        split_bf16(v1, h1, l1);
        uint32_t* wp = sm_w + (size_t)(((n * 64 + ks) * 32 + ln)) * 4;
        wp[reg]     = pack_bf2(h0, h1);
        wp[2 + reg] = pack_bf2(l0, l1);
    }

    float c_reg = 0.f, h_last = 0.f, bi = 0.f, bf_ = 0.f, bgt = 0.f, bo = 0.f;
    int pb = 0, pd = 0, pdg = 0, lane_c = 0, reg_c = 0;
    unsigned whoff = 0;
    int even = 0;
    unsigned myflag = (unsigned)(blockIdx.x >> 4);

    if (tid < 128) {
        pd  = tid & 7;
        pb  = tid >> 3;
        pdg = d0 + pd;
        int ksp  = pdg >> 4;
        int cc   = pdg & 15;
        int lnp  = (pb & 7) * 4 + ((cc & 7) >> 1);
        int regp = ((pb >> 3) & 1) + 2 * ((cc >> 3) & 1);
        whoff = (unsigned)((ksp * 32 + lnp) * 8 + 2 * regp);
        even  = ((cc & 1) == 0);
        lane_c = (pb & 7) * 4 + (pd >> 1);
        reg_c  = 2 * (pb >> 3) + (pd & 1);

        c_reg = carry[((size_t)pb * DD + pdg) * 2 + 1];
        float h0v = carry[((size_t)pb * DD + pdg) * 2 + 0];
        bi  = bias[pdg];
        bf_ = bias[DD + pdg];
        bgt = bias[2 * DD + pdg];
        bo  = bias[3 * DD + pdg];

        __nv_bfloat16 hhi, hlo;
        split_bf16(h0v, hhi, hlo);
        uint32_t v  = pack_bf2(hhi, hlo);
        uint32_t pv = __shfl_xor_sync(0xffffffffu, v, 1);
        if (even) {
            uint2 pr;
            pr.x = (v & 0xffffu) | ((pv & 0xffffu) << 16);
            pr.y = (v >> 16) | ((pv >> 16) << 16);
            *(uint2*)(g_hfrag[0] + whoff) = pr;
        }
    }
    __syncthreads();
    if (tid == 0) {
        asm volatile("red.release.gpu.global.add.u32 [%0], %1;"
                     :: "l"(&g_flags[myflag * 64]), "r"(1u) : "memory");
    }

    unsigned* const fp = &g_flags[(unsigned)w * 64];
    float* nc = dout + (size_t)BB * TT * DD;

    for (int t = 0; t < TT; ++t) {
        float xgi = 0.f, xgf = 0.f, xgg = 0.f, xgo = 0.f;
        if (tid < 128) {
            const float* xr = g_xg + ((size_t)pb * TT + t) * EE + pdg;
            xgi = __ldg(xr);
            xgf = __ldg(xr + DD);
            xgg = __ldg(xr + 2 * DD);
            xgo = __ldg(xr + 3 * DD);
        }

        {
            const unsigned tgt = (unsigned)(t + 1) * 16u;
            unsigned v;
            do {
                asm volatile("ld.global.acquire.gpu.u32 %0, [%1];"
                             : "=r"(v) : "l"(fp) : "memory");
            } while (v < tgt);
        }

        float4 acc[4];
#pragma unroll
        for (int n = 0; n < 4; ++n) acc[n] = make_float4(0.f, 0.f, 0.f, 0.f);

        const uint4* ab = (const uint4*)g_hfrag[t & 1];
#pragma unroll
        for (int j = 0; j < 8; ++j) {
            int ks = w * 8 + j;
            uint4 q0 = __ldcg(ab + (ks * 32 + lane) * 2);
            uint4 q1 = __ldcg(ab + (ks * 32 + lane) * 2 + 1);
            uint4 ahi = make_uint4(q0.x, q0.z, q1.x, q1.z);
            uint4 alo = make_uint4(q0.y, q0.w, q1.y, q1.w);
#pragma unroll
            for (int n = 0; n < 4; ++n) {
                uint4 b = *(const uint4*)(sm_w + (size_t)(((n * 64 + ks) * 32 + lane)) * 4);
                mma_bf16(acc[n], ahi, b.x, b.y);
                mma_bf16(acc[n], ahi, b.z, b.w);
                mma_bf16(acc[n], alo, b.x, b.y);
            }
        }

        float* rb = red + (t & 1) * RED_FLOATS;
#pragma unroll
        for (int n = 0; n < 4; ++n) {
            *(float4*)(rb + (size_t)(((w * 4 + n) * 32 + lane)) * 4) = acc[n];
        }
        __syncthreads();

        if (tid < 128) {
            float gi = xgi + bi, gf = xgf + bf_, gg = xgg + bgt, go = xgo + bo;
#pragma unroll
            for (int q = 0; q < 8; ++q) {
                const float* rp = rb + (size_t)(q * 4) * 128;
                gi += rp[lane_c * 4 + reg_c];
                gf += rp[128 + lane_c * 4 + reg_c];
                gg += rp[256 + lane_c * 4 + reg_c];
                go += rp[384 + lane_c * 4 + reg_c];
            }
            float iv = fast_sigmoid(gi);
            float fv = fast_sigmoid(gf);
            float gv = fast_tanh(gg);
            float ov = fast_sigmoid(go);
            c_reg    = fv * c_reg + iv * gv;
            float hv = ov * fast_tanh(c_reg);
            h_last   = hv;

            if (t + 1 < TT) {
                __nv_bfloat16 hhi, hlo;
                split_bf16(hv, hhi, hlo);
                uint32_t v  = pack_bf2(hhi, hlo);
                uint32_t pv = __shfl_xor_sync(0xffffffffu, v, 1);
                if (even) {
                    uint2 pr;
                    pr.x = (v & 0xffffu) | ((pv & 0xffffu) << 16);
                    pr.y = (v >> 16) | ((pv >> 16) << 16);
                    *(uint2*)(g_hfrag[(t + 1) & 1] + whoff) = pr;
                }
                asm volatile("bar.sync 1, 128;" ::: "memory");
                if (tid == 0) {
                    asm volatile("red.release.gpu.global.add.u32 [%0], %1;"
                                 :: "l"(&g_flags[myflag * 64]), "r"(1u)
                                 : "memory");
                }
            }
            dout[((size_t)pb * TT + t) * DD + pdg] = hv;
        }
    }

    if (tid < 128) {
        nc[((size_t)pb * DD + pdg) * 2 + 0] = h_last;
        nc[((size_t)pb * DD + pdg) * 2 + 1] = c_reg;
    }

    __syncthreads();
    if (tid == 0) {
        __threadfence();
        unsigned r = atomicAdd(&g_endcnt, 1u);
        if ((r & 127u) == 127u) {
#pragma unroll
            for (int g = 0; g < 8; ++g) g_flags[g * 64] = 0u;
            __threadfence();
        }
    }
}

// ---------------------------------------------------------------------------
// Launch
// ---------------------------------------------------------------------------
extern "C" void kernel_launch(void* const* d_in, const int* in_sizes, int n_in,
                              void* d_out, int out_size) {
    (void)in_sizes; (void)n_in; (void)out_size;
    const float* x     = (const float*)d_in[0];
    const float* carry = (const float*)d_in[1];
    const float* Wi    = (const float*)d_in[2];
    const float* Wh    = (const float*)d_in[3];
    const float* b     = (const float*)d_in[4];
    float* out = (float*)d_out;

    {
        size_t nx4 = (size_t)BB * TT * DD / 4;
        size_t nw4 = (size_t)DD * EE / 4;
        convert_x<<<(unsigned)((nx4 + 255) / 256), 256>>>(x, nx4);
        split_wi<<<(unsigned)((nw4 + 255) / 256), 256>>>(Wi, nw4);
    }

    cudaFuncSetAttribute(gemm_xg_mma,
                         cudaFuncAttributeMaxDynamicSharedMemorySize,
                         GEMM_SMEM_BYTES);
    dim3 ggrid(EE / 128, (BB * TT) / 128);
    gemm_xg_mma<<<ggrid, 256, GEMM_SMEM_BYTES>>>();

    cudaFuncSetAttribute(lstm_rec_kernel,
                         cudaFuncAttributeMaxDynamicSharedMemorySize,
                         REC_SMEM_BYTES);
    lstm_rec_kernel<<<REC_BLOCKS, 256, REC_SMEM_BYTES>>>(carry, Wh, b, out);
}

// round 17
// speedup vs baseline: 2.6824x; 1.2394x over previous
#include <cuda_runtime.h>
#include <cuda_bf16.h>
#include <cuda_fp16.h>
#include <cstdint>
#include <cstddef>

// Problem constants: B=16, T=2048, D=1024, E=4D=4096
#define BB 16
#define TT 2048
#define DD 1024
#define EE 4096

#define REC_BLOCKS 128
#define DPB (DD / REC_BLOCKS)

// ---------------------------------------------------------------------------
// Device scratch
// ---------------------------------------------------------------------------
__device__ float g_xg[(size_t)BB * TT * EE];

__device__ __half g_xh[(size_t)BB * TT * DD];      // x hi (fp16)
__device__ __half g_wihi[(size_t)DD * EE];         // Wi hi (fp16)
__device__ __half g_wilo[(size_t)DD * EE];         // Wi lo (fp16)

// h in mma A-fragment order, fp16 HI plane only: [64 ks][32 lanes][4 words].
// 32 KB per buffer.
__device__ __align__(16) uint32_t g_hfrag[2][64 * 32 * 4];

// R5-proven flag scheme: one counter per k-group (warp 0..7), 256 B apart.
__device__ unsigned g_flags[8 * 64];
__device__ unsigned g_endcnt;

// ---------------------------------------------------------------------------
// Helpers
// ---------------------------------------------------------------------------
__device__ __forceinline__ void mma4_f16(float* c, const uint32_t* a,
                                         uint32_t b0, uint32_t b1) {
    asm volatile(
        "mma.sync.aligned.m16n8k16.row.col.f32.f16.f16.f32 "
        "{%0,%1,%2,%3}, {%4,%5,%6,%7}, {%8,%9}, {%0,%1,%2,%3};\n"
        : "+f"(c[0]), "+f"(c[1]), "+f"(c[2]), "+f"(c[3])
        : "r"(a[0]), "r"(a[1]), "r"(a[2]), "r"(a[3]), "r"(b0), "r"(b1));
}

__device__ __forceinline__ void mma_f16v(float4& c, const uint4& a,
                                         uint32_t b0, uint32_t b1) {
    asm volatile(
        "mma.sync.aligned.m16n8k16.row.col.f32.f16.f16.f32 "
        "{%0,%1,%2,%3}, {%4,%5,%6,%7}, {%8,%9}, {%0,%1,%2,%3};\n"
        : "+f"(c.x), "+f"(c.y), "+f"(c.z), "+f"(c.w)
        : "r"(a.x), "r"(a.y), "r"(a.z), "r"(a.w), "r"(b0), "r"(b1));
}

__device__ __forceinline__ void ldsm_x4(uint32_t* r, uint32_t addr) {
    asm volatile("ldmatrix.sync.aligned.m8n8.x4.shared.b16 {%0,%1,%2,%3}, [%4];"
        : "=r"(r[0]), "=r"(r[1]), "=r"(r[2]), "=r"(r[3]) : "r"(addr));
}
__device__ __forceinline__ void ldsm_x4_t(uint32_t* r, uint32_t addr) {
    asm volatile("ldmatrix.sync.aligned.m8n8.x4.trans.shared.b16 {%0,%1,%2,%3}, [%4];"
        : "=r"(r[0]), "=r"(r[1]), "=r"(r[2]), "=r"(r[3]) : "r"(addr));
}

__device__ __forceinline__ void split_f16(float v, __half& hi, __half& lo) {
    hi = __float2half_rn(v);
    lo = __float2half_rn(v - __half2float(hi));
}

__device__ __forceinline__ uint32_t pack_h2(__half a, __half b) {
    return (uint32_t)__half_as_ushort(a) |
           ((uint32_t)__half_as_ushort(b) << 16);
}

__device__ __forceinline__ float fast_sigmoid(float x) {
    return __fdividef(1.f, 1.f + __expf(-x));
}
__device__ __forceinline__ float fast_tanh(float x) {
    return __fdividef(2.f, 1.f + __expf(-2.f * x)) - 1.f;
}

#define CP_ASYNC16(dst, src) \
    asm volatile("cp.async.cg.shared.global [%0], [%1], 16;" \
                 :: "r"(dst), "l"(src))
#define CP_COMMIT() asm volatile("cp.async.commit_group;" ::: "memory")
#define CP_WAIT2()  asm volatile("cp.async.wait_group 2;" ::: "memory")

// ---------------------------------------------------------------------------
// Phase 0a: x fp32 -> fp16 hi plane only
// ---------------------------------------------------------------------------
__global__ __launch_bounds__(256) void convert_x(
    const float* __restrict__ src, size_t n4)
{
    size_t i = (size_t)blockIdx.x * 256 + threadIdx.x;
    if (i >= n4) return;
    float4 v = ((const float4*)src)[i];
    uint2 o;
    o.x = pack_h2(__float2half_rn(v.x), __float2half_rn(v.y));
    o.y = pack_h2(__float2half_rn(v.z), __float2half_rn(v.w));
    ((uint2*)g_xh)[i] = o;
}

// ---------------------------------------------------------------------------
// Phase 0b: Wi fp32 -> fp16 hi/lo planes
// ---------------------------------------------------------------------------
__global__ __launch_bounds__(256) void split_wi(
    const float* __restrict__ src, size_t n4)
{
    size_t i = (size_t)blockIdx.x * 256 + threadIdx.x;
    if (i >= n4) return;
    float4 v = ((const float4*)src)[i];
    __half h[4], l[4];
    split_f16(v.x, h[0], l[0]);
    split_f16(v.y, h[1], l[1]);
    split_f16(v.z, h[2], l[2]);
    split_f16(v.w, h[3], l[3]);
    ((uint2*)g_wihi)[i] = make_uint2(pack_h2(h[0], h[1]), pack_h2(h[2], h[3]));
    ((uint2*)g_wilo)[i] = make_uint2(pack_h2(l[0], l[1]), pack_h2(l[2], l[3]));
}

// ---------------------------------------------------------------------------
// Phase 1: xg = x @ Wi — fp16 2-pass MMA, cp.async 3-stage (R16, unchanged)
// ---------------------------------------------------------------------------
#define A_STRIDE 40
#define B_STRIDE 136
#define A_PLANE (128 * A_STRIDE)
#define B_PLANE (32 * B_STRIDE)
#define STAGE_ELEMS (A_PLANE + 2 * B_PLANE)
#define STAGE_BYTES (STAGE_ELEMS * 2)
#define GEMM_SMEM_BYTES (3 * STAGE_BYTES)

__global__ __launch_bounds__(256) void gemm_xg_mma(void)
{
    extern __shared__ __align__(16) __half gsm[];

    const int tid  = threadIdx.x;
    const int lane = tid & 31;
    const int w    = tid >> 5;
    const int wn   = w >> 2;
    const int wm   = w & 3;
    const int m0   = blockIdx.y * 128;
    const int n0   = blockIdx.x * 128;

    const uint32_t smem_u32 = (uint32_t)__cvta_generic_to_shared(gsm);

    auto issue_stage = [&](int stage, int kt) {
        const int k0 = kt * 32;
        uint32_t sb = smem_u32 + stage * STAGE_BYTES;
#pragma unroll
        for (int r = 0; r < 2; ++r) {
            int chunk = tid + 256 * r;
            int row   = chunk >> 2;
            int c8    = (chunk & 3) * 8;
            const __half* sh = g_xh + (size_t)(m0 + row) * DD + k0 + c8;
            CP_ASYNC16(sb + (uint32_t)(row * A_STRIDE + c8) * 2, sh);
        }
        uint32_t bb = sb + 2 * A_PLANE;
#pragma unroll
        for (int r = 0; r < 2; ++r) {
            int chunk = tid + 256 * r;
            int row   = chunk >> 4;
            int c8    = (chunk & 15) * 8;
            const __half* sh = g_wihi + (size_t)(k0 + row) * EE + n0 + c8;
            const __half* sl = g_wilo + (size_t)(k0 + row) * EE + n0 + c8;
            uint32_t dh = bb + (uint32_t)(row * B_STRIDE + c8) * 2;
            uint32_t dl = dh + B_PLANE * 2;
            CP_ASYNC16(dh, sh);
            CP_ASYNC16(dl, sl);
        }
    };

    float acc[2][8][4];
#pragma unroll
    for (int mt = 0; mt < 2; ++mt)
#pragma unroll
        for (int nt = 0; nt < 8; ++nt)
#pragma unroll
            for (int i = 0; i < 4; ++i) acc[mt][nt][i] = 0.f;

    issue_stage(0, 0); CP_COMMIT();
    issue_stage(1, 1); CP_COMMIT();
    issue_stage(2, 2); CP_COMMIT();

    for (int it = 0; it < 32; ++it) {
        CP_WAIT2();
        __syncthreads();

        const int stage = it % 3;
        const uint32_t aBase = smem_u32 + stage * STAGE_BYTES;
        const uint32_t bBase = aBase + 2 * A_PLANE;

#pragma unroll
        for (int ks = 0; ks < 2; ++ks) {
            uint32_t afr[2][4];
#pragma unroll
            for (int mt = 0; mt < 2; ++mt) {
                uint32_t addr = aBase
                    + (uint32_t)((wm * 32 + mt * 16 + (lane & 15)) * (A_STRIDE * 2))
                    + (uint32_t)((ks * 16 + (lane >> 4) * 8) * 2);
                ldsm_x4(afr[mt], addr);
            }
            uint32_t bfr[4][2][4];
#pragma unroll
            for (int np = 0; np < 4; ++np)
#pragma unroll
                for (int p = 0; p < 2; ++p) {
                    uint32_t addr = bBase + p * (B_PLANE * 2)
                        + (uint32_t)((ks * 16 + (lane & 15)) * (B_STRIDE * 2))
                        + (uint32_t)((wn * 64 + np * 16 + (lane >> 4) * 8) * 2);
                    ldsm_x4_t(bfr[np][p], addr);
                }
#pragma unroll
            for (int mt = 0; mt < 2; ++mt)
#pragma unroll
                for (int np = 0; np < 4; ++np)
#pragma unroll
                    for (int hf = 0; hf < 2; ++hf) {
                        int nt = np * 2 + hf;
                        float* c = acc[mt][nt];
                        mma4_f16(c, afr[mt], bfr[np][0][hf * 2],
                                 bfr[np][0][hf * 2 + 1]);
                        mma4_f16(c, afr[mt], bfr[np][1][hf * 2],
                                 bfr[np][1][hf * 2 + 1]);
                    }
        }
        __syncthreads();
        if (it + 3 < 32) issue_stage(stage, it + 3);
        CP_COMMIT();
    }

#pragma unroll
    for (int mt = 0; mt < 2; ++mt)
#pragma unroll
        for (int nt = 0; nt < 8; ++nt) {
            int row = m0 + wm * 32 + mt * 16 + (lane >> 2);
            int col = n0 + wn * 64 + nt * 8 + (lane & 3) * 2;
            float* c = acc[mt][nt];
            __stcs((float2*)(g_xg + (size_t)row * EE + col),
                   make_float2(c[0], c[1]));
            __stcs((float2*)(g_xg + (size_t)(row + 8) * EE + col),
                   make_float2(c[2], c[3]));
        }
}

// ---------------------------------------------------------------------------
// Phase 2: persistent recurrence — R5 protocol, fp16 2-pass MMA.
// h published as fp16 hi plane only (32 KB/buffer); Wh hi/lo fp16 in smem;
// per (ks,n): acc += a_hi*b_hi + a_hi*b_lo  (2 MMAs, was 3).
// ---------------------------------------------------------------------------
#define W_WORDS (4 * 64 * 32 * 4)
#define RED_FLOATS (8 * 4 * 32 * 4)
#define REC_SMEM_BYTES (W_WORDS * 4 + 2 * RED_FLOATS * 4)

__global__ __launch_bounds__(256, 1) void lstm_rec_kernel(
    const float* __restrict__ carry,
    const float* __restrict__ Wh,
    const float* __restrict__ bias,
    float* __restrict__ dout)
{
    extern __shared__ uint32_t sm_w[];
    float* red = (float*)(sm_w + W_WORDS);

    const int tid  = threadIdx.x;
    const int w    = tid >> 5;
    const int lane = tid & 31;
    const int d0   = blockIdx.x * DPB;

    // pack Wh slice into smem as mma B fragments (hi/lo fp16)
    for (int idx = tid; idx < 4 * 64 * 32 * 2; idx += 256) {
        int n    = idx >> 12;
        int rem  = idx & 4095;
        int ks   = rem >> 6;
        int rem2 = rem & 63;
        int ln   = rem2 >> 1;
        int reg  = rem2 & 1;
        int tig  = ln & 3;
        int dl   = ln >> 2;
        int kb   = ks * 16 + reg * 8 + tig * 2;
        size_t col = (size_t)n * DD + d0 + dl;
        float v0 = Wh[(size_t)kb * EE + col];
        float v1 = Wh[(size_t)(kb + 1) * EE + col];
        __half h0, l0, h1, l1;
        split_f16(v0, h0, l0);
        split_f16(v1, h1, l1);
        uint32_t* wp = sm_w + (size_t)(((n * 64 + ks) * 32 + ln)) * 4;
        wp[reg]     = pack_h2(h0, h1);
        wp[2 + reg] = pack_h2(l0, l1);
    }

    float c_reg = 0.f, h_last = 0.f, bi = 0.f, bf_ = 0.f, bgt = 0.f, bo = 0.f;
    int pb = 0, pd = 0, pdg = 0, lane_c = 0, reg_c = 0;
    unsigned whoff = 0;          // u32 word offset of my fragment word
    int even = 0;
    unsigned myflag = (unsigned)(blockIdx.x >> 4);

    if (tid < 128) {
        pd  = tid & 7;
        pb  = tid >> 3;
        pdg = d0 + pd;
        int ksp  = pdg >> 4;
        int cc   = pdg & 15;
        int lnp  = (pb & 7) * 4 + ((cc & 7) >> 1);
        int regp = ((pb >> 3) & 1) + 2 * ((cc >> 3) & 1);
        whoff = (unsigned)((ksp * 32 + lnp) * 4 + regp);
        even  = ((cc & 1) == 0);
        lane_c = (pb & 7) * 4 + (pd >> 1);
        reg_c  = 2 * (pb >> 3) + (pd & 1);

        c_reg = carry[((size_t)pb * DD + pdg) * 2 + 1];
        float h0v = carry[((size_t)pb * DD + pdg) * 2 + 0];
        bi  = bias[pdg];
        bf_ = bias[DD + pdg];
        bgt = bias[2 * DD + pdg];
        bo  = bias[3 * DD + pdg];

        uint32_t v  = (uint32_t)__half_as_ushort(__float2half_rn(h0v));
        uint32_t pv = __shfl_xor_sync(0xffffffffu, v, 1);
        if (even) g_hfrag[0][whoff] = v | (pv << 16);
    }
    __syncthreads();
    if (tid == 0) {
        asm volatile("red.release.gpu.global.add.u32 [%0], %1;"
                     :: "l"(&g_flags[myflag * 64]), "r"(1u) : "memory");
    }

    unsigned* const fp = &g_flags[(unsigned)w * 64];
    float* nc = dout + (size_t)BB * TT * DD;

    for (int t = 0; t < TT; ++t) {
        float xgi = 0.f, xgf = 0.f, xgg = 0.f, xgo = 0.f;
        if (tid < 128) {
            const float* xr = g_xg + ((size_t)pb * TT + t) * EE + pdg;
            xgi = __ldg(xr);
            xgf = __ldg(xr + DD);
            xgg = __ldg(xr + 2 * DD);
            xgo = __ldg(xr + 3 * DD);
        }

        {
            const unsigned tgt = (unsigned)(t + 1) * 16u;
            unsigned v;
            do {
                asm volatile("ld.global.acquire.gpu.u32 %0, [%1];"
                             : "=r"(v) : "l"(fp) : "memory");
            } while (v < tgt);
        }

        float4 acc[4];
#pragma unroll
        for (int n = 0; n < 4; ++n) acc[n] = make_float4(0.f, 0.f, 0.f, 0.f);

        const uint4* ab = (const uint4*)g_hfrag[t & 1];
#pragma unroll
        for (int j = 0; j < 8; ++j) {
            int ks = w * 8 + j;
            uint4 ahi = __ldcg(ab + (ks * 32 + lane));   // one LDG.128
#pragma unroll
            for (int n = 0; n < 4; ++n) {
                uint4 b = *(const uint4*)(sm_w + (size_t)(((n * 64 + ks) * 32 + lane)) * 4);
                mma_f16v(acc[n], ahi, b.x, b.y);   // hi * hi
                mma_f16v(acc[n], ahi, b.z, b.w);   // hi * lo
            }
        }

        float* rb = red + (t & 1) * RED_FLOATS;
#pragma unroll
        for (int n = 0; n < 4; ++n) {
            *(float4*)(rb + (size_t)(((w * 4 + n) * 32 + lane)) * 4) = acc[n];
        }
        __syncthreads();

        if (tid < 128) {
            float gi = xgi + bi, gf = xgf + bf_, gg = xgg + bgt, go = xgo + bo;
#pragma unroll
            for (int q = 0; q < 8; ++q) {
                const float* rp = rb + (size_t)(q * 4) * 128;
                gi += rp[lane_c * 4 + reg_c];
                gf += rp[128 + lane_c * 4 + reg_c];
                gg += rp[256 + lane_c * 4 + reg_c];
                go += rp[384 + lane_c * 4 + reg_c];
            }
            float iv = fast_sigmoid(gi);
            float fv = fast_sigmoid(gf);
            float gv = fast_tanh(gg);
            float ov = fast_sigmoid(go);
            c_reg    = fv * c_reg + iv * gv;
            float hv = ov * fast_tanh(c_reg);
            h_last   = hv;

            if (t + 1 < TT) {
                uint32_t v  = (uint32_t)__half_as_ushort(__float2half_rn(hv));
                uint32_t pv = __shfl_xor_sync(0xffffffffu, v, 1);
                if (even) g_hfrag[(t + 1) & 1][whoff] = v | (pv << 16);
                asm volatile("bar.sync 1, 128;" ::: "memory");
                if (tid == 0) {
                    asm volatile("red.release.gpu.global.add.u32 [%0], %1;"
                                 :: "l"(&g_flags[myflag * 64]), "r"(1u)
                                 : "memory");
                }
            }
            dout[((size_t)pb * TT + t) * DD + pdg] = hv;
        }
    }

    if (tid < 128) {
        nc[((size_t)pb * DD + pdg) * 2 + 0] = h_last;
        nc[((size_t)pb * DD + pdg) * 2 + 1] = c_reg;
    }

    __syncthreads();
    if (tid == 0) {
        __threadfence();
        unsigned r = atomicAdd(&g_endcnt, 1u);
        if ((r & 127u) == 127u) {
#pragma unroll
            for (int g = 0; g < 8; ++g) g_flags[g * 64] = 0u;
            __threadfence();
        }
    }
}

// ---------------------------------------------------------------------------
// Launch
// ---------------------------------------------------------------------------
extern "C" void kernel_launch(void* const* d_in, const int* in_sizes, int n_in,
                              void* d_out, int out_size) {
    (void)in_sizes; (void)n_in; (void)out_size;
    const float* x     = (const float*)d_in[0];
    const float* carry = (const float*)d_in[1];
    const float* Wi    = (const float*)d_in[2];
    const float* Wh    = (const float*)d_in[3];
    const float* b     = (const float*)d_in[4];
    float* out = (float*)d_out;

    {
        size_t nx4 = (size_t)BB * TT * DD / 4;
        size_t nw4 = (size_t)DD * EE / 4;
        convert_x<<<(unsigned)((nx4 + 255) / 256), 256>>>(x, nx4);
        split_wi<<<(unsigned)((nw4 + 255) / 256), 256>>>(Wi, nw4);
    }

    cudaFuncSetAttribute(gemm_xg_mma,
                         cudaFuncAttributeMaxDynamicSharedMemorySize,
                         GEMM_SMEM_BYTES);
    dim3 ggrid(EE / 128, (BB * TT) / 128);
    gemm_xg_mma<<<ggrid, 256, GEMM_SMEM_BYTES>>>();

    cudaFuncSetAttribute(lstm_rec_kernel,
                         cudaFuncAttributeMaxDynamicSharedMemorySize,
                         REC_SMEM_BYTES);
    lstm_rec_kernel<<<REC_BLOCKS, 256, REC_SMEM_BYTES>>>(carry, Wh, b, out);
}